// round 1
// baseline (speedup 1.0000x reference)
#include <cuda_runtime.h>
#include <math.h>

#define G_     8
#define CIN_   32
#define COUT_  32
#define HID_   32
#define KS_    7
#define NTAP_  49
#define NCH_   256        // CIN_*G_
#define B_     16
#define H_     64
#define W_     64
#define HW_    4096
#define OMEGA_ 10.0f
#define TILE   16
#define XS     22         // TILE + KS_ - 1

// [gout][c=cin*8+gin][tap][cout]  : 8*256*49*32 floats = 12.8 MB
__device__ float d_wbuf[G_ * NCH_ * NTAP_ * COUT_];
__device__ int   d_nt[G_];
__device__ int   d_tap[G_ * NTAP_];

// Replicate jnp.linspace(-1, 1, 7) in fp32 exactly: v = fl(i * fl(2/6)) + (-1),
// endpoint forced to stop (== 1.0f here anyway).
__device__ __forceinline__ float grid_val(int i) {
    if (i == 6) return 1.0f;
    const float step = 2.0f / 6.0f;   // fl32(0.3333333433)
    return __fadd_rn(__fmul_rn((float)i, step), -1.0f);
}

// ---------------------------------------------------------------------------
// Mask + active-tap list per gout. Mirrors JAX fp32 ops (no FMA contraction,
// libdevice sinf/cosf) because the 4 axis taps sit exactly on ||p|| == 1.
// ---------------------------------------------------------------------------
__global__ void mask_kernel(const float* __restrict__ g_elems) {
    __shared__ int msk[NTAP_];
    int g = blockIdx.x;
    float th = g_elems[g];
    float ct = cosf(-th);
    float st = sinf(-th);
    int t = threadIdx.x;
    if (t < NTAP_) {
        float y = grid_val(t / KS_);
        float x = grid_val(t % KS_);
        float ny = __fadd_rn(__fmul_rn(ct, y), -__fmul_rn(st, x));
        float nx = __fadd_rn(__fmul_rn(st, y),  __fmul_rn(ct, x));
        float s  = __fadd_rn(__fmul_rn(ny, ny), __fmul_rn(nx, nx));
        msk[t] = (sqrtf(s) <= 1.0f) ? 1 : 0;
    }
    __syncthreads();
    if (t == 0) {
        int n = 0;
        for (int i = 0; i < NTAP_; i++)
            if (msk[i]) d_tap[g * NTAP_ + n++] = i;
        d_nt[g] = n;
    }
}

// ---------------------------------------------------------------------------
// SIREN kernel-net: one block per (gout, gin). 49 points -> 49*1024 weights.
// ---------------------------------------------------------------------------
__global__ void siren_kernel(const float* __restrict__ g_elems,
                             const float* __restrict__ W1, const float* __restrict__ b1,
                             const float* __restrict__ W2, const float* __restrict__ b2,
                             const float* __restrict__ W3, const float* __restrict__ b3) {
    __shared__ float pts[NTAP_ * 3];
    __shared__ float h1[NTAP_ * HID_];
    __shared__ float h2[NTAP_ * HID_];

    int gout = blockIdx.x >> 3;
    int gin  = blockIdx.x & 7;
    int tid  = threadIdx.x;

    if (tid < NTAP_) {
        float tho = g_elems[gout];
        float thi = g_elems[gin];
        float ct = cosf(-tho);
        float st = sinf(-tho);
        const float twopi = 6.28318530717958647692f;  // fl32(2*pi)
        const float pif   = 3.14159265358979323846f;  // fl32(pi)
        // acted_g = mod(thi - tho, 2pi)/pi - 1  (jnp.mod semantics; |d| < 2pi)
        float d = __fadd_rn(thi, -tho);
        float m = fmodf(d, twopi);
        if (m < 0.0f) m = __fadd_rn(m, twopi);
        float ag = __fadd_rn(__fdiv_rn(m, pif), -1.0f);

        float y = grid_val(tid / KS_);
        float x = grid_val(tid % KS_);
        pts[tid * 3 + 0] = __fadd_rn(__fmul_rn(ct, y), -__fmul_rn(st, x));
        pts[tid * 3 + 1] = __fadd_rn(__fmul_rn(st, y),  __fmul_rn(ct, x));
        pts[tid * 3 + 2] = ag;
    }
    __syncthreads();

    // layer 1: 3 -> 32, sin(omega * (.))
    for (int i = tid; i < NTAP_ * HID_; i += 256) {
        int t = i >> 5, h = i & 31;
        float v = b1[h];
        v = fmaf(pts[t * 3 + 0], W1[0 * HID_ + h], v);
        v = fmaf(pts[t * 3 + 1], W1[1 * HID_ + h], v);
        v = fmaf(pts[t * 3 + 2], W1[2 * HID_ + h], v);
        h1[i] = sinf(OMEGA_ * v);
    }
    __syncthreads();

    // layer 2: 32 -> 32, sin(omega * (.))
    for (int i = tid; i < NTAP_ * HID_; i += 256) {
        int t = i >> 5, h = i & 31;
        float v = b2[h];
#pragma unroll
        for (int k = 0; k < HID_; k++)
            v = fmaf(h1[t * HID_ + k], W2[k * HID_ + h], v);
        h2[i] = sinf(OMEGA_ * v);
    }
    __syncthreads();

    // layer 3: 32 -> 1024 (cout*32 + cin), scatter into conv weight layout
    for (int i = tid; i < NTAP_ * 1024; i += 256) {
        int t = i >> 10, o = i & 1023;
        float v = b3[o];
#pragma unroll
        for (int k = 0; k < HID_; k++)
            v = fmaf(h2[t * HID_ + k], W3[k * 1024 + o], v);
        int cout = o >> 5, cin = o & 31;
        int c = cin * G_ + gin;
        d_wbuf[(((size_t)gout * NCH_ + c) * NTAP_ + t) * COUT_ + cout] = v;
    }
}

// ---------------------------------------------------------------------------
// Direct conv: block = (b, gout) x 16x16 tile. 256 threads, each 4 px x 8 cout.
// Loops 256 input channels; per channel stages halo tile + active-tap weights
// in smem. Inner loop: 4 LDS(x) + 2 LDS.128(w) + 32 FFMA per tap.
// ---------------------------------------------------------------------------
__global__ __launch_bounds__(256, 2)
void conv_kernel(const float* __restrict__ x, const float* __restrict__ bias,
                 float* __restrict__ out) {
    __shared__ float xs[XS * XS];
    __shared__ float ws[NTAP_ * COUT_];
    __shared__ int   toff[NTAP_];
    __shared__ int   tidxs[NTAP_];
    __shared__ int   nt_s;

    int tid  = threadIdx.x;
    int bz   = blockIdx.z;
    int gout = bz & 7;
    int b    = bz >> 3;
    int h0   = blockIdx.y * TILE;
    int w0   = blockIdx.x * TILE;

    if (tid == 0) nt_s = d_nt[gout];
    if (tid < NTAP_) {
        int tp = d_tap[gout * NTAP_ + tid];
        tidxs[tid] = tp;
        toff[tid]  = (tp / KS_) * XS + (tp % KS_);
    }

    int cg = tid >> 6;          // cout group 0..3 (8 couts each)
    int pg = tid & 63;          // pixel group
    int pr = pg >> 2;           // row 0..15
    int pc = (pg & 3) << 2;     // col base 0,4,8,12

    float acc[8][4];
#pragma unroll
    for (int k = 0; k < 8; k++)
#pragma unroll
        for (int j = 0; j < 4; j++) acc[k][j] = 0.0f;

    __syncthreads();
    int nt = nt_s;

    const float* xb  = x + (size_t)b * NCH_ * HW_;
    const float* wgb = d_wbuf + (size_t)gout * NCH_ * NTAP_ * COUT_;

    for (int c = 0; c < NCH_; c++) {
        // stage input halo (22x22, zero-padded)
        const float* xc = xb + (size_t)c * HW_;
        for (int i = tid; i < XS * XS; i += 256) {
            int r = i / XS, q = i - r * XS;
            int hh = h0 - 3 + r, ww = w0 - 3 + q;
            xs[i] = (hh >= 0 && hh < H_ && ww >= 0 && ww < W_)
                        ? __ldg(xc + hh * W_ + ww) : 0.0f;
        }
        // stage weights for active taps
        const float* wc = wgb + (size_t)c * (NTAP_ * COUT_);
        for (int i = tid; i < nt * COUT_; i += 256) {
            int t = i >> 5, co = i & 31;
            ws[i] = __ldg(wc + tidxs[t] * COUT_ + co);
        }
        __syncthreads();

        const float* xrow = xs + pr * XS + pc;
        const float4* wsv = (const float4*)ws;
        for (int t = 0; t < nt; t++) {
            const float* xp = xrow + toff[t];
            float xv[4];
            xv[0] = xp[0]; xv[1] = xp[1]; xv[2] = xp[2]; xv[3] = xp[3];
            float4 wa = wsv[t * 8 + cg * 2];
            float4 wb = wsv[t * 8 + cg * 2 + 1];
            float wv[8] = {wa.x, wa.y, wa.z, wa.w, wb.x, wb.y, wb.z, wb.w};
#pragma unroll
            for (int k = 0; k < 8; k++)
#pragma unroll
                for (int j = 0; j < 4; j++)
                    acc[k][j] = fmaf(xv[j], wv[k], acc[k][j]);
        }
        __syncthreads();
    }

    // epilogue: out[b][cout][gout][h][w] + bias[cout]
    int h = h0 + pr, w = w0 + pc;
#pragma unroll
    for (int k = 0; k < 8; k++) {
        int cout = cg * 8 + k;
        float bv = bias[cout];
        float4 v = make_float4(acc[k][0] + bv, acc[k][1] + bv,
                               acc[k][2] + bv, acc[k][3] + bv);
        *(float4*)(out + ((((size_t)b * COUT_ + cout) * G_ + gout) * H_ + h) * W_ + w) = v;
    }
}

extern "C" void kernel_launch(void* const* d_in, const int* in_sizes, int n_in,
                              void* d_out, int out_size) {
    const float* x    = (const float*)d_in[0];
    const float* ge   = (const float*)d_in[1];
    const float* W1   = (const float*)d_in[2];
    const float* b1   = (const float*)d_in[3];
    const float* W2   = (const float*)d_in[4];
    const float* b2   = (const float*)d_in[5];
    const float* W3   = (const float*)d_in[6];
    const float* b3   = (const float*)d_in[7];
    const float* bias = (const float*)d_in[8];
    float* out = (float*)d_out;

    mask_kernel<<<G_, 64>>>(ge);
    siren_kernel<<<G_ * G_, 256>>>(ge, W1, b1, W2, b2, W3, b3);
    dim3 grid(W_ / TILE, H_ / TILE, B_ * G_);
    conv_kernel<<<grid, 256>>>(x, bias, out);
}

// round 3
// speedup vs baseline: 3.2234x; 3.2234x over previous
#include <cuda_runtime.h>
#include <cuda_bf16.h>
#include <math.h>
#include <stdint.h>

#define G_     8
#define KS_    7
#define NTAP_  49
#define HID_   32
#define OMEGA_ 10.0f

// ---------------------------------------------------------------------------
// Device globals (static — no allocation)
// ---------------------------------------------------------------------------
__device__ __align__(256) __nv_bfloat16 d_Ah[2 * NTAP_ * 4 * 128 * 64];   // 6.4MB
__device__ __align__(256) __nv_bfloat16 d_Al[2 * NTAP_ * 4 * 128 * 64];
__device__ __align__(256) __nv_bfloat16 d_xTh[16 * 4096 * 256];           // 33.5MB
__device__ __align__(256) __nv_bfloat16 d_xTl[16 * 4096 * 256];
__device__ int d_mask[G_ * NTAP_];
__device__ int d_utap[NTAP_];
__device__ int d_nu;

// ---------------------------------------------------------------------------
// PTX helpers (baseline sm_80-class only: compiles for .target sm_103)
// ---------------------------------------------------------------------------
__device__ __forceinline__ uint32_t smem_u32(const void* p) {
    uint32_t a;
    asm("{ .reg .u64 t; cvta.to.shared.u64 t, %1; cvt.u32.u64 %0, t; }" : "=r"(a) : "l"(p));
    return a;
}
__device__ __forceinline__ void cp16(uint32_t dst, const void* src, uint32_t sz) {
    asm volatile("cp.async.cg.shared.global [%0], [%1], 16, %2;"
                 :: "r"(dst), "l"(src), "r"(sz) : "memory");
}
#define CP_COMMIT() asm volatile("cp.async.commit_group;" ::: "memory")
#define CP_WAIT1()  asm volatile("cp.async.wait_group 1;" ::: "memory")
#define CP_WAIT0()  asm volatile("cp.async.wait_group 0;" ::: "memory")

__device__ __forceinline__ void ldsm4(uint32_t* r, uint32_t a) {
    asm volatile("ldmatrix.sync.aligned.m8n8.x4.shared.b16 {%0,%1,%2,%3}, [%4];"
                 : "=r"(r[0]), "=r"(r[1]), "=r"(r[2]), "=r"(r[3]) : "r"(a));
}
__device__ __forceinline__ void mma16816(float* d, const uint32_t* a, const uint32_t* b) {
    asm volatile(
        "mma.sync.aligned.m16n8k16.row.col.f32.bf16.bf16.f32 "
        "{%0,%1,%2,%3}, {%4,%5,%6,%7}, {%8,%9}, {%0,%1,%2,%3};"
        : "+f"(d[0]), "+f"(d[1]), "+f"(d[2]), "+f"(d[3])
        : "r"(a[0]), "r"(a[1]), "r"(a[2]), "r"(a[3]), "r"(b[0]), "r"(b[1]));
}

// Replicate jnp.linspace(-1,1,7) fp32 exactly
__device__ __forceinline__ float grid_val(int i) {
    if (i == 6) return 1.0f;
    const float step = 2.0f / 6.0f;
    return __fadd_rn(__fmul_rn((float)i, step), -1.0f);
}

// ---------------------------------------------------------------------------
// Mask: per-gout disk masks + union tap list. Mirrors JAX fp32 op sequence.
// ---------------------------------------------------------------------------
__global__ void mask_kernel(const float* __restrict__ ge) {
    __shared__ int um[NTAP_];
    int t = threadIdx.x;
    if (t < NTAP_) {
        float y = grid_val(t / KS_);
        float x = grid_val(t % KS_);
        int u = 0;
        for (int g = 0; g < G_; g++) {
            float th = ge[g];
            float ct = cosf(-th), st = sinf(-th);
            float ny = __fadd_rn(__fmul_rn(ct, y), -__fmul_rn(st, x));
            float nx = __fadd_rn(__fmul_rn(st, y),  __fmul_rn(ct, x));
            float ss = __fadd_rn(__fmul_rn(ny, ny), __fmul_rn(nx, nx));
            int mk = (sqrtf(ss) <= 1.0f) ? 1 : 0;
            d_mask[g * NTAP_ + t] = mk;
            u |= mk;
        }
        um[t] = u;
    }
    __syncthreads();
    if (t == 0) {
        int n = 0;
        for (int i = 0; i < NTAP_; i++)
            if (um[i]) d_utap[n++] = i;
        d_nu = n;
    }
}

// ---------------------------------------------------------------------------
// Transpose + bf16 hi/lo split: x[b][c][pix] -> xT[b][pix][c]
// ---------------------------------------------------------------------------
__global__ void xt_kernel(const float* __restrict__ x) {
    __shared__ float s[64][129];
    int p0 = blockIdx.x * 64;
    int b  = blockIdx.y;
    int c0 = blockIdx.z * 128;
    int tid = threadIdx.x;
    int c_off = tid >> 6;
    int px = tid & 63;
    const float* xb = x + (size_t)b * 256 * 4096 + p0 + px;
#pragma unroll 4
    for (int cb = 0; cb < 32; cb++) {
        int cl = cb * 4 + c_off;
        s[px][cl] = xb[(size_t)(c0 + cl) * 4096];
    }
    __syncthreads();
#pragma unroll
    for (int r = 0; r < 4; r++) {
        int idx = tid + r * 256;       // 0..1023
        int p = idx >> 4;              // 0..63
        int u = idx & 15;              // 16 uint4 per 128-ch half
        __nv_bfloat16 hb[8], lb[8];
#pragma unroll
        for (int e = 0; e < 8; e++) {
            float v = s[p][u * 8 + e];
            __nv_bfloat16 h = __float2bfloat16(v);
            hb[e] = h;
            lb[e] = __float2bfloat16(v - __bfloat162float(h));
        }
        size_t dst = ((size_t)b * 4096 + p0 + p) * 256 + c0 + u * 8;
        *(uint4*)(d_xTh + dst) = *(uint4*)hb;
        *(uint4*)(d_xTl + dst) = *(uint4*)lb;
    }
}

// ---------------------------------------------------------------------------
// SIREN kernel-net -> masked bf16 hi/lo A tiles [mt][tap][cc][m=128][k=64]
// ---------------------------------------------------------------------------
__global__ void siren_kernel(const float* __restrict__ ge,
                             const float* __restrict__ W1, const float* __restrict__ b1,
                             const float* __restrict__ W2, const float* __restrict__ b2,
                             const float* __restrict__ W3, const float* __restrict__ b3) {
    __shared__ float pts[NTAP_ * 3];
    __shared__ float h1[NTAP_ * HID_];
    __shared__ float h2[NTAP_ * HID_];
    __shared__ int   s_mask[NTAP_];

    int gout = blockIdx.x >> 3;
    int gin  = blockIdx.x & 7;
    int tid  = threadIdx.x;

    if (tid < NTAP_) {
        s_mask[tid] = d_mask[gout * NTAP_ + tid];
        float tho = ge[gout];
        float thi = ge[gin];
        float ct = cosf(-tho);
        float st = sinf(-tho);
        const float twopi = 6.28318530717958647692f;
        const float pif   = 3.14159265358979323846f;
        float d = __fadd_rn(thi, -tho);
        float m = fmodf(d, twopi);
        if (m < 0.0f) m = __fadd_rn(m, twopi);
        float ag = __fadd_rn(__fdiv_rn(m, pif), -1.0f);
        float y = grid_val(tid / KS_);
        float x = grid_val(tid % KS_);
        pts[tid * 3 + 0] = __fadd_rn(__fmul_rn(ct, y), -__fmul_rn(st, x));
        pts[tid * 3 + 1] = __fadd_rn(__fmul_rn(st, y),  __fmul_rn(ct, x));
        pts[tid * 3 + 2] = ag;
    }
    __syncthreads();

    for (int i = tid; i < NTAP_ * HID_; i += 256) {
        int t = i >> 5, h = i & 31;
        float v = b1[h];
        v = fmaf(pts[t * 3 + 0], W1[0 * HID_ + h], v);
        v = fmaf(pts[t * 3 + 1], W1[1 * HID_ + h], v);
        v = fmaf(pts[t * 3 + 2], W1[2 * HID_ + h], v);
        h1[i] = sinf(OMEGA_ * v);
    }
    __syncthreads();

    for (int i = tid; i < NTAP_ * HID_; i += 256) {
        int t = i >> 5, h = i & 31;
        float v = b2[h];
#pragma unroll
        for (int k = 0; k < HID_; k++)
            v = fmaf(h1[t * HID_ + k], W2[k * HID_ + h], v);
        h2[i] = sinf(OMEGA_ * v);
    }
    __syncthreads();

    for (int i = tid; i < NTAP_ * 1024; i += 256) {
        int t = i >> 10, o = i & 1023;
        float v = b3[o];
#pragma unroll
        for (int k = 0; k < HID_; k++)
            v = fmaf(h2[t * HID_ + k], W3[k * 1024 + o], v);
        if (!s_mask[t]) v = 0.0f;
        int cout = o >> 5, cin = o & 31;
        int c = cin * G_ + gin;
        int mt = gout >> 2, m = ((gout & 3) << 5) + cout;
        __nv_bfloat16 h = __float2bfloat16(v);
        __nv_bfloat16 l = __float2bfloat16(v - __bfloat162float(h));
        size_t addr = ((size_t)((mt * NTAP_ + t) * 4 + (c >> 6))) * 8192 + m * 64 + (c & 63);
        d_Ah[addr] = h;
        d_Al[addr] = l;
    }
}

// ---------------------------------------------------------------------------
// HMMA conv: block tile M=128 x N=256px, K-chunk=64 (tap x 64ch),
// 3-term bf16 split via mma.sync.m16n8k16, cp.async 2-stage pipeline.
// ---------------------------------------------------------------------------
#define ST_A_H   0
#define ST_A_L   16384
#define ST_B_H   32768
#define ST_B_L   65536
#define STAGE_SZ 98304
#define SM_BIAS  (2 * STAGE_SZ)
#define SM_UTAP  (SM_BIAS + 128)
#define SM_NU    (SM_UTAP + 4 * NTAP_)
#define SMEM_DYN (SM_NU + 16)

struct ConvCtx {
    uint32_t sbase;
    int tid, mt, b, h0;
    const int* utap;
};

__device__ __forceinline__ void stage_chunk(const ConvCtx& c, int i, int s) {
    int tap = c.utap[i >> 2];
    int cc  = i & 3;
    uint32_t stg = c.sbase + (uint32_t)s * STAGE_SZ;

    // A hi/lo: [128m x 64k] rows of 128B, 16B-XOR swizzle
    const char* gah = (const char*)(d_Ah + (size_t)((c.mt * NTAP_ + tap) * 4 + cc) * 8192);
    const char* gal = (const char*)(d_Al + (size_t)((c.mt * NTAP_ + tap) * 4 + cc) * 8192);
#pragma unroll
    for (int r = 0; r < 4; r++) {
        int idx = c.tid + (r << 8);
        int m = idx >> 3, u = idx & 7;
        uint32_t d = (uint32_t)(m * 128 + ((u * 16) ^ ((m & 7) << 4)));
        cp16(stg + ST_A_H + d, gah + idx * 16, 16);
        cp16(stg + ST_A_L + d, gal + idx * 16, 16);
    }
    // B hi/lo: 256 pixel rows x 64k (128B), thread = pixel
    int dy = tap / KS_ - 3, dx = tap % KS_ - 3;
    int hh = c.h0 + (c.tid >> 6) + dy;
    int ww = (c.tid & 63) + dx;
    bool ok = (hh >= 0) && (hh < 64) && (ww >= 0) && (ww < 64);
    size_t pix = ok ? ((size_t)c.b * 4096 + (size_t)hh * 64 + ww) : 0;
    const char* gbh = (const char*)(d_xTh + pix * 256 + cc * 64);
    const char* gbl = (const char*)(d_xTl + pix * 256 + cc * 64);
    uint32_t sz = ok ? 16u : 0u;
    uint32_t rowbase = (uint32_t)(c.tid * 128);
    uint32_t sw = (uint32_t)((c.tid & 7) << 4);
#pragma unroll
    for (int u = 0; u < 8; u++) {
        uint32_t d = rowbase + ((u * 16) ^ sw);
        cp16(stg + ST_B_H + d, gbh + u * 16, sz);
        cp16(stg + ST_B_L + d, gbl + u * 16, sz);
    }
}

__global__ void __launch_bounds__(256, 1)
conv_kernel(const float* __restrict__ bias, float* __restrict__ out) {
    extern __shared__ char sm[];
    uint32_t sbase = smem_u32(sm);
    int tid  = threadIdx.x;
    int lane = tid & 31;
    int wid  = tid >> 5;
    int wm   = wid & 1;     // M half (64 rows)
    int wn   = wid >> 1;    // N quarter (64 px = image row wn)

    if (tid < 32) ((float*)(sm + SM_BIAS))[tid] = bias[tid];
    if (tid < NTAP_) ((int*)(sm + SM_UTAP))[tid] = d_utap[tid];
    if (tid == 0) *((int*)(sm + SM_NU)) = d_nu;
    __syncthreads();

    ConvCtx c;
    c.sbase = sbase;
    c.tid = tid;
    c.utap = (const int*)(sm + SM_UTAP);
    int nu = *((const int*)(sm + SM_NU));
    int nc = nu << 2;

    int T  = blockIdx.x;
    c.mt   = T & 1;
    c.b    = (T >> 1) & 15;
    c.h0   = (T >> 5) << 2;

    float acc[4][8][4];
#pragma unroll
    for (int ms = 0; ms < 4; ms++)
#pragma unroll
        for (int nf = 0; nf < 8; nf++)
#pragma unroll
            for (int q = 0; q < 4; q++) acc[ms][nf][q] = 0.0f;

    stage_chunk(c, 0, 0);
    CP_COMMIT();

    for (int i = 0; i < nc; i++) {
        int s = i & 1;
        if (i + 1 < nc) {
            stage_chunk(c, i + 1, s ^ 1);
            CP_COMMIT();
            CP_WAIT1();
        } else {
            CP_WAIT0();
        }
        __syncthreads();

        uint32_t stg = sbase + (uint32_t)s * STAGE_SZ;
#pragma unroll
        for (int ks = 0; ks < 4; ks++) {
            uint32_t ah[4][4], al[4][4], bh[4][4], bl[4][4];
#pragma unroll
            for (int ms = 0; ms < 4; ms++) {
                int row = wm * 64 + ms * 16 + (lane & 15);
                uint32_t kb = (uint32_t)(ks * 32 + ((lane >> 4) << 4));
                uint32_t a = stg + (uint32_t)(row * 128) + (kb ^ ((row & 7) << 4));
                ldsm4(ah[ms], a + ST_A_H);
                ldsm4(al[ms], a + ST_A_L);
            }
#pragma unroll
            for (int ns = 0; ns < 4; ns++) {
                int row = wn * 64 + ns * 16 + (lane & 7) + ((lane & 16) >> 1);
                uint32_t kb = (uint32_t)(ks * 32 + ((lane & 8) << 1));
                uint32_t a = stg + (uint32_t)(row * 128) + (kb ^ ((row & 7) << 4));
                ldsm4(bh[ns], a + ST_B_H);
                ldsm4(bl[ns], a + ST_B_L);
            }
#pragma unroll
            for (int ms = 0; ms < 4; ms++)
#pragma unroll
                for (int nf = 0; nf < 8; nf++)
                    mma16816(acc[ms][nf], ah[ms], &bh[nf >> 1][(nf & 1) * 2]);
#pragma unroll
            for (int ms = 0; ms < 4; ms++)
#pragma unroll
                for (int nf = 0; nf < 8; nf++)
                    mma16816(acc[ms][nf], al[ms], &bh[nf >> 1][(nf & 1) * 2]);
#pragma unroll
            for (int ms = 0; ms < 4; ms++)
#pragma unroll
                for (int nf = 0; nf < 8; nf++)
                    mma16816(acc[ms][nf], ah[ms], &bl[nf >> 1][(nf & 1) * 2]);
        }
        __syncthreads();
    }

    // epilogue: out[b][cout][gout][h][w] + bias[cout]
    const float* sb = (const float*)(sm + SM_BIAS);
    int h = c.h0 + wn;
#pragma unroll
    for (int ms = 0; ms < 4; ms++) {
#pragma unroll
        for (int half = 0; half < 2; half++) {
            int rm = wm * 64 + ms * 16 + (lane >> 2) + half * 8;
            int gout = c.mt * 4 + (rm >> 5);
            int cout = rm & 31;
            float bv = sb[cout];
            float* ob = out + (((size_t)c.b * 32 + cout) * 8 + gout) * 4096 + h * 64;
#pragma unroll
            for (int nf = 0; nf < 8; nf++) {
                int w = nf * 8 + (lane & 3) * 2;
                float2 v;
                v.x = acc[ms][nf][half * 2 + 0] + bv;
                v.y = acc[ms][nf][half * 2 + 1] + bv;
                *(float2*)(ob + w) = v;
            }
        }
    }
}

// ---------------------------------------------------------------------------
extern "C" void kernel_launch(void* const* d_in, const int* in_sizes, int n_in,
                              void* d_out, int out_size) {
    const float* x    = (const float*)d_in[0];
    const float* ge   = (const float*)d_in[1];
    const float* W1   = (const float*)d_in[2];
    const float* b1   = (const float*)d_in[3];
    const float* W2   = (const float*)d_in[4];
    const float* b2   = (const float*)d_in[5];
    const float* W3   = (const float*)d_in[6];
    const float* b3   = (const float*)d_in[7];
    const float* bias = (const float*)d_in[8];
    float* out = (float*)d_out;

    cudaFuncSetAttribute(conv_kernel, cudaFuncAttributeMaxDynamicSharedMemorySize, SMEM_DYN);

    mask_kernel<<<1, 64>>>(ge);
    xt_kernel<<<dim3(64, 16, 2), 256>>>(x);
    siren_kernel<<<G_ * G_, 256>>>(ge, W1, b1, W2, b2, W3, b3);
    conv_kernel<<<512, 256, SMEM_DYN>>>(bias, out);
}

// round 4
// speedup vs baseline: 3.7093x; 1.1507x over previous
#include <cuda_runtime.h>
#include <cuda_bf16.h>
#include <math.h>
#include <stdint.h>

#define G_     8
#define KS_    7
#define NTAP_  49
#define HID_   32
#define OMEGA_ 10.0f

// ---------------------------------------------------------------------------
// Device globals (static — no allocation)
// ---------------------------------------------------------------------------
__device__ __align__(256) __nv_bfloat16 d_Ah[2 * NTAP_ * 4 * 128 * 64];   // 6.4MB
__device__ __align__(256) __nv_bfloat16 d_Al[2 * NTAP_ * 4 * 128 * 64];
__device__ __align__(256) __nv_bfloat16 d_xTh[16 * 4096 * 256];           // 33.5MB
__device__ __align__(256) __nv_bfloat16 d_xTl[16 * 4096 * 256];
__device__ int d_mask[G_ * NTAP_];
__device__ int d_utap[NTAP_];
__device__ int d_nu;

// ---------------------------------------------------------------------------
// PTX helpers (baseline sm_80-class only: compiles for .target sm_103)
// ---------------------------------------------------------------------------
__device__ __forceinline__ uint32_t smem_u32(const void* p) {
    uint32_t a;
    asm("{ .reg .u64 t; cvta.to.shared.u64 t, %1; cvt.u32.u64 %0, t; }" : "=r"(a) : "l"(p));
    return a;
}
__device__ __forceinline__ void cp16(uint32_t dst, const void* src, uint32_t sz) {
    asm volatile("cp.async.cg.shared.global [%0], [%1], 16, %2;"
                 :: "r"(dst), "l"(src), "r"(sz) : "memory");
}
#define CP_COMMIT() asm volatile("cp.async.commit_group;" ::: "memory")
#define CP_WAIT1()  asm volatile("cp.async.wait_group 1;" ::: "memory")
#define CP_WAIT0()  asm volatile("cp.async.wait_group 0;" ::: "memory")

__device__ __forceinline__ void ldsm4(uint32_t* r, uint32_t a) {
    asm volatile("ldmatrix.sync.aligned.m8n8.x4.shared.b16 {%0,%1,%2,%3}, [%4];"
                 : "=r"(r[0]), "=r"(r[1]), "=r"(r[2]), "=r"(r[3]) : "r"(a));
}
__device__ __forceinline__ void mma16816(float* d, const uint32_t* a, const uint32_t* b) {
    asm volatile(
        "mma.sync.aligned.m16n8k16.row.col.f32.bf16.bf16.f32 "
        "{%0,%1,%2,%3}, {%4,%5,%6,%7}, {%8,%9}, {%0,%1,%2,%3};"
        : "+f"(d[0]), "+f"(d[1]), "+f"(d[2]), "+f"(d[3])
        : "r"(a[0]), "r"(a[1]), "r"(a[2]), "r"(a[3]), "r"(b[0]), "r"(b[1]));
}

// Replicate jnp.linspace(-1,1,7) fp32 exactly
__device__ __forceinline__ float grid_val(int i) {
    if (i == 6) return 1.0f;
    const float step = 2.0f / 6.0f;
    return __fadd_rn(__fmul_rn((float)i, step), -1.0f);
}

// ---------------------------------------------------------------------------
// Mask: per-gout disk masks + union tap list. Mirrors JAX fp32 op sequence.
// ---------------------------------------------------------------------------
__global__ void mask_kernel(const float* __restrict__ ge) {
    __shared__ int um[NTAP_];
    int t = threadIdx.x;
    if (t < NTAP_) {
        float y = grid_val(t / KS_);
        float x = grid_val(t % KS_);
        int u = 0;
        for (int g = 0; g < G_; g++) {
            float th = ge[g];
            float ct = cosf(-th), st = sinf(-th);
            float ny = __fadd_rn(__fmul_rn(ct, y), -__fmul_rn(st, x));
            float nx = __fadd_rn(__fmul_rn(st, y),  __fmul_rn(ct, x));
            float ss = __fadd_rn(__fmul_rn(ny, ny), __fmul_rn(nx, nx));
            int mk = (sqrtf(ss) <= 1.0f) ? 1 : 0;
            d_mask[g * NTAP_ + t] = mk;
            u |= mk;
        }
        um[t] = u;
    }
    __syncthreads();
    if (t == 0) {
        int n = 0;
        for (int i = 0; i < NTAP_; i++)
            if (um[i]) d_utap[n++] = i;
        d_nu = n;
    }
}

// ---------------------------------------------------------------------------
// Transpose + bf16 hi/lo split: x[b][c][pix] -> xT[b][pix][c]
// ---------------------------------------------------------------------------
__global__ void xt_kernel(const float* __restrict__ x) {
    __shared__ float s[64][129];
    int p0 = blockIdx.x * 64;
    int b  = blockIdx.y;
    int c0 = blockIdx.z * 128;
    int tid = threadIdx.x;
    int c_off = tid >> 6;
    int px = tid & 63;
    const float* xb = x + (size_t)b * 256 * 4096 + p0 + px;
#pragma unroll 4
    for (int cb = 0; cb < 32; cb++) {
        int cl = cb * 4 + c_off;
        s[px][cl] = xb[(size_t)(c0 + cl) * 4096];
    }
    __syncthreads();
#pragma unroll
    for (int r = 0; r < 4; r++) {
        int idx = tid + r * 256;       // 0..1023
        int p = idx >> 4;              // 0..63
        int u = idx & 15;              // 16 uint4 per 128-ch half
        __nv_bfloat16 hb[8], lb[8];
#pragma unroll
        for (int e = 0; e < 8; e++) {
            float v = s[p][u * 8 + e];
            __nv_bfloat16 h = __float2bfloat16(v);
            hb[e] = h;
            lb[e] = __float2bfloat16(v - __bfloat162float(h));
        }
        size_t dst = ((size_t)b * 4096 + p0 + p) * 256 + c0 + u * 8;
        *(uint4*)(d_xTh + dst) = *(uint4*)hb;
        *(uint4*)(d_xTl + dst) = *(uint4*)lb;
    }
}

// ---------------------------------------------------------------------------
// SIREN kernel-net -> masked bf16 hi/lo A tiles [mt][tap][cc][m=128][k=64]
// ---------------------------------------------------------------------------
__global__ void siren_kernel(const float* __restrict__ ge,
                             const float* __restrict__ W1, const float* __restrict__ b1,
                             const float* __restrict__ W2, const float* __restrict__ b2,
                             const float* __restrict__ W3, const float* __restrict__ b3) {
    __shared__ float pts[NTAP_ * 3];
    __shared__ float h1[NTAP_ * HID_];
    __shared__ float h2[NTAP_ * HID_];
    __shared__ int   s_mask[NTAP_];

    int gout = blockIdx.x >> 3;
    int gin  = blockIdx.x & 7;
    int tid  = threadIdx.x;

    if (tid < NTAP_) {
        s_mask[tid] = d_mask[gout * NTAP_ + tid];
        float tho = ge[gout];
        float thi = ge[gin];
        float ct = cosf(-tho);
        float st = sinf(-tho);
        const float twopi = 6.28318530717958647692f;
        const float pif   = 3.14159265358979323846f;
        float d = __fadd_rn(thi, -tho);
        float m = fmodf(d, twopi);
        if (m < 0.0f) m = __fadd_rn(m, twopi);
        float ag = __fadd_rn(__fdiv_rn(m, pif), -1.0f);
        float y = grid_val(tid / KS_);
        float x = grid_val(tid % KS_);
        pts[tid * 3 + 0] = __fadd_rn(__fmul_rn(ct, y), -__fmul_rn(st, x));
        pts[tid * 3 + 1] = __fadd_rn(__fmul_rn(st, y),  __fmul_rn(ct, x));
        pts[tid * 3 + 2] = ag;
    }
    __syncthreads();

    for (int i = tid; i < NTAP_ * HID_; i += 256) {
        int t = i >> 5, h = i & 31;
        float v = b1[h];
        v = fmaf(pts[t * 3 + 0], W1[0 * HID_ + h], v);
        v = fmaf(pts[t * 3 + 1], W1[1 * HID_ + h], v);
        v = fmaf(pts[t * 3 + 2], W1[2 * HID_ + h], v);
        h1[i] = sinf(OMEGA_ * v);
    }
    __syncthreads();

    for (int i = tid; i < NTAP_ * HID_; i += 256) {
        int t = i >> 5, h = i & 31;
        float v = b2[h];
#pragma unroll
        for (int k = 0; k < HID_; k++)
            v = fmaf(h1[t * HID_ + k], W2[k * HID_ + h], v);
        h2[i] = sinf(OMEGA_ * v);
    }
    __syncthreads();

    for (int i = tid; i < NTAP_ * 1024; i += 256) {
        int t = i >> 10, o = i & 1023;
        float v = b3[o];
#pragma unroll
        for (int k = 0; k < HID_; k++)
            v = fmaf(h2[t * HID_ + k], W3[k * 1024 + o], v);
        if (!s_mask[t]) v = 0.0f;
        int cout = o >> 5, cin = o & 31;
        int c = cin * G_ + gin;
        int mt = gout >> 2, m = ((gout & 3) << 5) + cout;
        __nv_bfloat16 h = __float2bfloat16(v);
        __nv_bfloat16 l = __float2bfloat16(v - __bfloat162float(h));
        size_t addr = ((size_t)((mt * NTAP_ + t) * 4 + (c >> 6))) * 8192 + m * 64 + (c & 63);
        d_Ah[addr] = h;
        d_Al[addr] = l;
    }
}

// ---------------------------------------------------------------------------
// HMMA conv: 512 threads / 16 warps, block tile M=128 x N=256px, warp 64x32,
// K-chunk=64 (tap x 64ch), 3-term bf16 split, cp.async 2-stage pipeline.
// ---------------------------------------------------------------------------
#define ST_A_H   0
#define ST_A_L   16384
#define ST_B_H   32768
#define ST_B_L   65536
#define STAGE_SZ 98304
#define SM_BIAS  (2 * STAGE_SZ)
#define SM_UTAP  (SM_BIAS + 128)
#define SM_NU    (SM_UTAP + 4 * NTAP_)
#define SMEM_DYN (SM_NU + 16)

struct ConvCtx {
    uint32_t sbase;
    int tid, mt, b, h0;
    const int* utap;
};

__device__ __forceinline__ void stage_chunk(const ConvCtx& c, int i, int s) {
    int tap = c.utap[i >> 2];
    int cc  = i & 3;
    uint32_t stg = c.sbase + (uint32_t)s * STAGE_SZ;

    // A hi/lo: [128m x 64k] rows of 128B, 16B-XOR swizzle (2 uint4/thread each)
    const char* gah = (const char*)(d_Ah + (size_t)((c.mt * NTAP_ + tap) * 4 + cc) * 8192);
    const char* gal = (const char*)(d_Al + (size_t)((c.mt * NTAP_ + tap) * 4 + cc) * 8192);
#pragma unroll
    for (int r = 0; r < 2; r++) {
        int idx = c.tid + (r << 9);
        int m = idx >> 3, u = idx & 7;
        uint32_t d = (uint32_t)(m * 128 + ((u * 16) ^ ((m & 7) << 4)));
        cp16(stg + ST_A_H + d, gah + idx * 16, 16);
        cp16(stg + ST_A_L + d, gal + idx * 16, 16);
    }
    // B hi/lo: 256 pixel rows x 64k (128B); 2 threads per pixel, 4 uint4 each
    int dy = tap / KS_ - 3, dx = tap % KS_ - 3;
    int pix  = c.tid >> 1;
    int half = c.tid & 1;
    int hh = c.h0 + (pix >> 6) + dy;
    int ww = (pix & 63) + dx;
    bool ok = (hh >= 0) && (hh < 64) && (ww >= 0) && (ww < 64);
    size_t gpix = ok ? ((size_t)c.b * 4096 + (size_t)hh * 64 + ww) : 0;
    const char* gbh = (const char*)(d_xTh + gpix * 256 + cc * 64);
    const char* gbl = (const char*)(d_xTl + gpix * 256 + cc * 64);
    uint32_t sz = ok ? 16u : 0u;
    uint32_t rowbase = (uint32_t)(pix * 128);
    uint32_t sw = (uint32_t)((pix & 7) << 4);
#pragma unroll
    for (int u = 0; u < 4; u++) {
        int uu = half * 4 + u;
        uint32_t d = rowbase + ((uu * 16) ^ sw);
        cp16(stg + ST_B_H + d, gbh + uu * 16, sz);
        cp16(stg + ST_B_L + d, gbl + uu * 16, sz);
    }
}

__global__ void __launch_bounds__(512, 1)
conv_kernel(const float* __restrict__ bias, float* __restrict__ out) {
    extern __shared__ char sm[];
    uint32_t sbase = smem_u32(sm);
    int tid  = threadIdx.x;
    int lane = tid & 31;
    int wid  = tid >> 5;
    int wm   = wid & 1;     // M half (64 rows)
    int wn   = wid >> 1;    // N 32-px block (0..7)

    if (tid < 32) ((float*)(sm + SM_BIAS))[tid] = bias[tid];
    if (tid < NTAP_) ((int*)(sm + SM_UTAP))[tid] = d_utap[tid];
    if (tid == 0) *((int*)(sm + SM_NU)) = d_nu;
    __syncthreads();

    ConvCtx c;
    c.sbase = sbase;
    c.tid = tid;
    c.utap = (const int*)(sm + SM_UTAP);
    int nu = *((const int*)(sm + SM_NU));
    int nc = nu << 2;

    int T  = blockIdx.x;
    c.mt   = T & 1;
    c.b    = (T >> 1) & 15;
    c.h0   = (T >> 5) << 2;

    float acc[4][4][4];
#pragma unroll
    for (int ms = 0; ms < 4; ms++)
#pragma unroll
        for (int nf = 0; nf < 4; nf++)
#pragma unroll
            for (int q = 0; q < 4; q++) acc[ms][nf][q] = 0.0f;

    stage_chunk(c, 0, 0);
    CP_COMMIT();

    for (int i = 0; i < nc; i++) {
        int s = i & 1;
        if (i + 1 < nc) {
            stage_chunk(c, i + 1, s ^ 1);
            CP_COMMIT();
            CP_WAIT1();
        } else {
            CP_WAIT0();
        }
        __syncthreads();

        uint32_t stg = sbase + (uint32_t)s * STAGE_SZ;
#pragma unroll
        for (int ks = 0; ks < 4; ks++) {
            uint32_t ah[4][4], al[4][4], bh[2][4], bl[2][4];
#pragma unroll
            for (int ms = 0; ms < 4; ms++) {
                int row = wm * 64 + ms * 16 + (lane & 15);
                uint32_t kb = (uint32_t)(ks * 32 + ((lane >> 4) << 4));
                uint32_t a = stg + (uint32_t)(row * 128) + (kb ^ ((row & 7) << 4));
                ldsm4(ah[ms], a + ST_A_H);
                ldsm4(al[ms], a + ST_A_L);
            }
#pragma unroll
            for (int ns = 0; ns < 2; ns++) {
                int row = wn * 32 + ns * 16 + (lane & 7) + ((lane & 16) >> 1);
                uint32_t kb = (uint32_t)(ks * 32 + ((lane & 8) << 1));
                uint32_t a = stg + (uint32_t)(row * 128) + (kb ^ ((row & 7) << 4));
                ldsm4(bh[ns], a + ST_B_H);
                ldsm4(bl[ns], a + ST_B_L);
            }
#pragma unroll
            for (int ms = 0; ms < 4; ms++)
#pragma unroll
                for (int nf = 0; nf < 4; nf++)
                    mma16816(acc[ms][nf], ah[ms], &bh[nf >> 1][(nf & 1) * 2]);
#pragma unroll
            for (int ms = 0; ms < 4; ms++)
#pragma unroll
                for (int nf = 0; nf < 4; nf++)
                    mma16816(acc[ms][nf], al[ms], &bh[nf >> 1][(nf & 1) * 2]);
#pragma unroll
            for (int ms = 0; ms < 4; ms++)
#pragma unroll
                for (int nf = 0; nf < 4; nf++)
                    mma16816(acc[ms][nf], ah[ms], &bl[nf >> 1][(nf & 1) * 2]);
        }
        __syncthreads();
    }

    // epilogue: out[b][cout][gout][h][w] + bias[cout]
    const float* sb = (const float*)(sm + SM_BIAS);
    int h = c.h0 + (wn >> 1);
    int wbase = (wn & 1) * 32;
#pragma unroll
    for (int ms = 0; ms < 4; ms++) {
#pragma unroll
        for (int half = 0; half < 2; half++) {
            int rm = wm * 64 + ms * 16 + (lane >> 2) + half * 8;
            int gout = c.mt * 4 + (rm >> 5);
            int cout = rm & 31;
            float bv = sb[cout];
            float* ob = out + (((size_t)c.b * 32 + cout) * 8 + gout) * 4096 + h * 64;
#pragma unroll
            for (int nf = 0; nf < 4; nf++) {
                int w = wbase + nf * 8 + (lane & 3) * 2;
                float2 v;
                v.x = acc[ms][nf][half * 2 + 0] + bv;
                v.y = acc[ms][nf][half * 2 + 1] + bv;
                *(float2*)(ob + w) = v;
            }
        }
    }
}

// ---------------------------------------------------------------------------
extern "C" void kernel_launch(void* const* d_in, const int* in_sizes, int n_in,
                              void* d_out, int out_size) {
    const float* x    = (const float*)d_in[0];
    const float* ge   = (const float*)d_in[1];
    const float* W1   = (const float*)d_in[2];
    const float* b1   = (const float*)d_in[3];
    const float* W2   = (const float*)d_in[4];
    const float* b2   = (const float*)d_in[5];
    const float* W3   = (const float*)d_in[6];
    const float* b3   = (const float*)d_in[7];
    const float* bias = (const float*)d_in[8];
    float* out = (float*)d_out;

    cudaFuncSetAttribute(conv_kernel, cudaFuncAttributeMaxDynamicSharedMemorySize, SMEM_DYN);

    mask_kernel<<<1, 64>>>(ge);
    xt_kernel<<<dim3(64, 16, 2), 256>>>(x);
    siren_kernel<<<G_ * G_, 256>>>(ge, W1, b1, W2, b2, W3, b3);
    conv_kernel<<<512, 512, SMEM_DYN>>>(bias, out);
}

// round 5
// speedup vs baseline: 5.8287x; 1.5714x over previous
#include <cuda_runtime.h>
#include <cuda_bf16.h>
#include <cuda_fp16.h>
#include <math.h>
#include <stdint.h>

#define G_     8
#define KS_    7
#define NTAP_  49
#define HID_   32
#define OMEGA_ 10.0f

// ---------------------------------------------------------------------------
// Device globals (static — no allocation)
// ---------------------------------------------------------------------------
__device__ __align__(256) __half d_Ah[2 * NTAP_ * 4 * 128 * 64];   // 3.2MB
__device__ __align__(256) __half d_Al[2 * NTAP_ * 4 * 128 * 64];
__device__ __align__(256) __half d_xT[16 * 4096 * 256];            // 16.8MB
__device__ int d_mask[G_ * NTAP_];
__device__ int d_utap[NTAP_];
__device__ int d_nu;

// ---------------------------------------------------------------------------
// PTX helpers (baseline sm_80-class only: compiles for .target sm_103)
// ---------------------------------------------------------------------------
__device__ __forceinline__ uint32_t smem_u32(const void* p) {
    uint32_t a;
    asm("{ .reg .u64 t; cvta.to.shared.u64 t, %1; cvt.u32.u64 %0, t; }" : "=r"(a) : "l"(p));
    return a;
}
__device__ __forceinline__ void cp16(uint32_t dst, const void* src, uint32_t sz) {
    asm volatile("cp.async.cg.shared.global [%0], [%1], 16, %2;"
                 :: "r"(dst), "l"(src), "r"(sz) : "memory");
}
#define CP_COMMIT() asm volatile("cp.async.commit_group;" ::: "memory")
#define CP_WAIT1()  asm volatile("cp.async.wait_group 1;" ::: "memory")

__device__ __forceinline__ void ldsm4(uint32_t* r, uint32_t a) {
    asm volatile("ldmatrix.sync.aligned.m8n8.x4.shared.b16 {%0,%1,%2,%3}, [%4];"
                 : "=r"(r[0]), "=r"(r[1]), "=r"(r[2]), "=r"(r[3]) : "r"(a));
}
__device__ __forceinline__ void mma16816(float* d, const uint32_t* a, const uint32_t* b) {
    asm volatile(
        "mma.sync.aligned.m16n8k16.row.col.f32.f16.f16.f32 "
        "{%0,%1,%2,%3}, {%4,%5,%6,%7}, {%8,%9}, {%0,%1,%2,%3};"
        : "+f"(d[0]), "+f"(d[1]), "+f"(d[2]), "+f"(d[3])
        : "r"(a[0]), "r"(a[1]), "r"(a[2]), "r"(a[3]), "r"(b[0]), "r"(b[1]));
}

// Replicate jnp.linspace(-1,1,7) fp32 exactly
__device__ __forceinline__ float grid_val(int i) {
    if (i == 6) return 1.0f;
    const float step = 2.0f / 6.0f;
    return __fadd_rn(__fmul_rn((float)i, step), -1.0f);
}

// ---------------------------------------------------------------------------
// Mask: per-gout disk masks + union tap list. Mirrors JAX fp32 op sequence.
// ---------------------------------------------------------------------------
__global__ void mask_kernel(const float* __restrict__ ge) {
    __shared__ int um[NTAP_];
    int t = threadIdx.x;
    if (t < NTAP_) {
        float y = grid_val(t / KS_);
        float x = grid_val(t % KS_);
        int u = 0;
        for (int g = 0; g < G_; g++) {
            float th = ge[g];
            float ct = cosf(-th), st = sinf(-th);
            float ny = __fadd_rn(__fmul_rn(ct, y), -__fmul_rn(st, x));
            float nx = __fadd_rn(__fmul_rn(st, y),  __fmul_rn(ct, x));
            float ss = __fadd_rn(__fmul_rn(ny, ny), __fmul_rn(nx, nx));
            int mk = (sqrtf(ss) <= 1.0f) ? 1 : 0;
            d_mask[g * NTAP_ + t] = mk;
            u |= mk;
        }
        um[t] = u;
    }
    __syncthreads();
    if (t == 0) {
        int n = 0;
        for (int i = 0; i < NTAP_; i++)
            if (um[i]) d_utap[n++] = i;
        d_nu = n;
    }
}

// ---------------------------------------------------------------------------
// Transpose + fp16 convert: x[b][c][pix] -> xT[b][pix][c]
// ---------------------------------------------------------------------------
__global__ void xt_kernel(const float* __restrict__ x) {
    __shared__ float s[64][129];
    int p0 = blockIdx.x * 64;
    int b  = blockIdx.y;
    int c0 = blockIdx.z * 128;
    int tid = threadIdx.x;
    int c_off = tid >> 6;
    int px = tid & 63;
    const float* xb = x + (size_t)b * 256 * 4096 + p0 + px;
#pragma unroll 4
    for (int cb = 0; cb < 32; cb++) {
        int cl = cb * 4 + c_off;
        s[px][cl] = xb[(size_t)(c0 + cl) * 4096];
    }
    __syncthreads();
#pragma unroll
    for (int r = 0; r < 4; r++) {
        int idx = tid + r * 256;       // 0..1023
        int p = idx >> 4;              // 0..63
        int u = idx & 15;              // 16 uint4 per 128-ch half
        __half hb[8];
#pragma unroll
        for (int e = 0; e < 8; e++)
            hb[e] = __float2half_rn(s[p][u * 8 + e]);
        size_t dst = ((size_t)b * 4096 + p0 + p) * 256 + c0 + u * 8;
        *(uint4*)(d_xT + dst) = *(uint4*)hb;
    }
}

// ---------------------------------------------------------------------------
// SIREN kernel-net -> masked fp16 hi/lo A tiles [mt][tap][cc][m=128][k=64]
// ---------------------------------------------------------------------------
__global__ void siren_kernel(const float* __restrict__ ge,
                             const float* __restrict__ W1, const float* __restrict__ b1,
                             const float* __restrict__ W2, const float* __restrict__ b2,
                             const float* __restrict__ W3, const float* __restrict__ b3) {
    __shared__ float pts[NTAP_ * 3];
    __shared__ float h1[NTAP_ * HID_];
    __shared__ float h2[NTAP_ * HID_];
    __shared__ int   s_mask[NTAP_];

    int gout = blockIdx.x >> 3;
    int gin  = blockIdx.x & 7;
    int tid  = threadIdx.x;

    if (tid < NTAP_) {
        s_mask[tid] = d_mask[gout * NTAP_ + tid];
        float tho = ge[gout];
        float thi = ge[gin];
        float ct = cosf(-tho);
        float st = sinf(-tho);
        const float twopi = 6.28318530717958647692f;
        const float pif   = 3.14159265358979323846f;
        float d = __fadd_rn(thi, -tho);
        float m = fmodf(d, twopi);
        if (m < 0.0f) m = __fadd_rn(m, twopi);
        float ag = __fadd_rn(__fdiv_rn(m, pif), -1.0f);
        float y = grid_val(tid / KS_);
        float x = grid_val(tid % KS_);
        pts[tid * 3 + 0] = __fadd_rn(__fmul_rn(ct, y), -__fmul_rn(st, x));
        pts[tid * 3 + 1] = __fadd_rn(__fmul_rn(st, y),  __fmul_rn(ct, x));
        pts[tid * 3 + 2] = ag;
    }
    __syncthreads();

    for (int i = tid; i < NTAP_ * HID_; i += 256) {
        int t = i >> 5, h = i & 31;
        float v = b1[h];
        v = fmaf(pts[t * 3 + 0], W1[0 * HID_ + h], v);
        v = fmaf(pts[t * 3 + 1], W1[1 * HID_ + h], v);
        v = fmaf(pts[t * 3 + 2], W1[2 * HID_ + h], v);
        h1[i] = sinf(OMEGA_ * v);
    }
    __syncthreads();

    for (int i = tid; i < NTAP_ * HID_; i += 256) {
        int t = i >> 5, h = i & 31;
        float v = b2[h];
#pragma unroll
        for (int k = 0; k < HID_; k++)
            v = fmaf(h1[t * HID_ + k], W2[k * HID_ + h], v);
        h2[i] = sinf(OMEGA_ * v);
    }
    __syncthreads();

    for (int i = tid; i < NTAP_ * 1024; i += 256) {
        int t = i >> 10, o = i & 1023;
        float v = b3[o];
#pragma unroll
        for (int k = 0; k < HID_; k++)
            v = fmaf(h2[t * HID_ + k], W3[k * 1024 + o], v);
        if (!s_mask[t]) v = 0.0f;
        int cout = o >> 5, cin = o & 31;
        int c = cin * G_ + gin;
        int mt = gout >> 2, m = ((gout & 3) << 5) + cout;
        __half h = __float2half_rn(v);
        __half l = __float2half_rn(v - __half2float(h));
        size_t addr = ((size_t)((mt * NTAP_ + t) * 4 + (c >> 6))) * 8192 + m * 64 + (c & 63);
        d_Ah[addr] = h;
        d_Al[addr] = l;
    }
}

// ---------------------------------------------------------------------------
// HMMA conv: 512 threads / 16 warps, block tile M=128 x N=256px, warp 64x32,
// K-chunk=64 (tap x 64ch), fp16 2-term split (A hi/lo, B single fp16),
// 3-stage cp.async pipeline, one __syncthreads per chunk.
// ---------------------------------------------------------------------------
#define ST_A_H   0
#define ST_A_L   16384
#define ST_B     32768
#define STAGE_SZ 65536
#define SM_BIAS  (3 * STAGE_SZ)
#define SM_UTAP  (SM_BIAS + 128)
#define SM_NU    (SM_UTAP + 4 * NTAP_)
#define SMEM_DYN (SM_NU + 16)

struct ConvCtx {
    uint32_t sbase;
    int tid, mt, b, h0;
    const int* utap;
};

__device__ __forceinline__ void stage_chunk(const ConvCtx& c, int i, int s) {
    int tap = c.utap[i >> 2];
    int cc  = i & 3;
    uint32_t stg = c.sbase + (uint32_t)s * STAGE_SZ;

    // A hi/lo: [128m x 64k] rows of 128B, 16B-XOR swizzle (2 uint4/thread each)
    const char* gah = (const char*)(d_Ah + (size_t)((c.mt * NTAP_ + tap) * 4 + cc) * 8192);
    const char* gal = (const char*)(d_Al + (size_t)((c.mt * NTAP_ + tap) * 4 + cc) * 8192);
#pragma unroll
    for (int r = 0; r < 2; r++) {
        int idx = c.tid + (r << 9);
        int m = idx >> 3, u = idx & 7;
        uint32_t d = (uint32_t)(m * 128 + ((u * 16) ^ ((m & 7) << 4)));
        cp16(stg + ST_A_H + d, gah + idx * 16, 16);
        cp16(stg + ST_A_L + d, gal + idx * 16, 16);
    }
    // B: 256 pixel rows x 64k (128B); 2 threads per pixel, 4 uint4 each
    int dy = tap / KS_ - 3, dx = tap % KS_ - 3;
    int pix  = c.tid >> 1;
    int half = c.tid & 1;
    int hh = c.h0 + (pix >> 6) + dy;
    int ww = (pix & 63) + dx;
    bool ok = (hh >= 0) && (hh < 64) && (ww >= 0) && (ww < 64);
    size_t gpix = ok ? ((size_t)c.b * 4096 + (size_t)hh * 64 + ww) : 0;
    const char* gb = (const char*)(d_xT + gpix * 256 + cc * 64);
    uint32_t sz = ok ? 16u : 0u;
    uint32_t rowbase = (uint32_t)(pix * 128);
    uint32_t sw = (uint32_t)((pix & 7) << 4);
#pragma unroll
    for (int u = 0; u < 4; u++) {
        int uu = half * 4 + u;
        uint32_t d = rowbase + ((uu * 16) ^ sw);
        cp16(stg + ST_B + d, gb + uu * 16, sz);
    }
}

__global__ void __launch_bounds__(512, 1)
conv_kernel(const float* __restrict__ bias, float* __restrict__ out) {
    extern __shared__ char sm[];
    uint32_t sbase = smem_u32(sm);
    int tid  = threadIdx.x;
    int lane = tid & 31;
    int wid  = tid >> 5;
    int wm   = wid & 1;     // M half (64 rows)
    int wn   = wid >> 1;    // N 32-px block (0..7)

    if (tid < 32) ((float*)(sm + SM_BIAS))[tid] = bias[tid];
    if (tid < NTAP_) ((int*)(sm + SM_UTAP))[tid] = d_utap[tid];
    if (tid == 0) *((int*)(sm + SM_NU)) = d_nu;
    __syncthreads();

    ConvCtx c;
    c.sbase = sbase;
    c.tid = tid;
    c.utap = (const int*)(sm + SM_UTAP);
    int nu = *((const int*)(sm + SM_NU));
    int nc = nu << 2;

    int T  = blockIdx.x;
    c.mt   = T & 1;
    c.b    = (T >> 1) & 15;
    c.h0   = (T >> 5) << 2;

    float acc[4][4][4];
#pragma unroll
    for (int ms = 0; ms < 4; ms++)
#pragma unroll
        for (int nf = 0; nf < 4; nf++)
#pragma unroll
            for (int q = 0; q < 4; q++) acc[ms][nf][q] = 0.0f;

    stage_chunk(c, 0, 0);
    CP_COMMIT();
    stage_chunk(c, 1, 1);
    CP_COMMIT();

    int s = 0;
    for (int i = 0; i < nc; i++) {
        CP_WAIT1();                 // stage i resident (i+1 may be in flight)
        __syncthreads();            // also: everyone finished compute(i-1)
        if (i + 2 < nc) {           // prefetch into buffer (i+2)%3 == (i-1)%3
            int s2 = s + 2; if (s2 >= 3) s2 -= 3;
            stage_chunk(c, i + 2, s2);
            CP_COMMIT();
        }

        uint32_t stg = sbase + (uint32_t)s * STAGE_SZ;
#pragma unroll
        for (int ks = 0; ks < 4; ks++) {
            uint32_t ah[4][4], al[4][4], bf[2][4];
#pragma unroll
            for (int ms = 0; ms < 4; ms++) {
                int row = wm * 64 + ms * 16 + (lane & 15);
                uint32_t kb = (uint32_t)(ks * 32 + ((lane >> 4) << 4));
                uint32_t a = stg + (uint32_t)(row * 128) + (kb ^ ((row & 7) << 4));
                ldsm4(ah[ms], a + ST_A_H);
                ldsm4(al[ms], a + ST_A_L);
            }
#pragma unroll
            for (int ns = 0; ns < 2; ns++) {
                int row = wn * 32 + ns * 16 + (lane & 7) + ((lane & 16) >> 1);
                uint32_t kb = (uint32_t)(ks * 32 + ((lane & 8) << 1));
                uint32_t a = stg + (uint32_t)(row * 128) + (kb ^ ((row & 7) << 4));
                ldsm4(bf[ns], a + ST_B);
            }
#pragma unroll
            for (int ms = 0; ms < 4; ms++)
#pragma unroll
                for (int nf = 0; nf < 4; nf++)
                    mma16816(acc[ms][nf], ah[ms], &bf[nf >> 1][(nf & 1) * 2]);
#pragma unroll
            for (int ms = 0; ms < 4; ms++)
#pragma unroll
                for (int nf = 0; nf < 4; nf++)
                    mma16816(acc[ms][nf], al[ms], &bf[nf >> 1][(nf & 1) * 2]);
        }
        if (++s >= 3) s = 0;
    }

    // epilogue: out[b][cout][gout][h][w] + bias[cout]
    const float* sb = (const float*)(sm + SM_BIAS);
    int h = c.h0 + (wn >> 1);
    int wbase = (wn & 1) * 32;
#pragma unroll
    for (int ms = 0; ms < 4; ms++) {
#pragma unroll
        for (int half = 0; half < 2; half++) {
            int rm = wm * 64 + ms * 16 + (lane >> 2) + half * 8;
            int gout = c.mt * 4 + (rm >> 5);
            int cout = rm & 31;
            float bv = sb[cout];
            float* ob = out + (((size_t)c.b * 32 + cout) * 8 + gout) * 4096 + h * 64;
#pragma unroll
            for (int nf = 0; nf < 4; nf++) {
                int w = wbase + nf * 8 + (lane & 3) * 2;
                float2 v;
                v.x = acc[ms][nf][half * 2 + 0] + bv;
                v.y = acc[ms][nf][half * 2 + 1] + bv;
                *(float2*)(ob + w) = v;
            }
        }
    }
}

// ---------------------------------------------------------------------------
extern "C" void kernel_launch(void* const* d_in, const int* in_sizes, int n_in,
                              void* d_out, int out_size) {
    const float* x    = (const float*)d_in[0];
    const float* ge   = (const float*)d_in[1];
    const float* W1   = (const float*)d_in[2];
    const float* b1   = (const float*)d_in[3];
    const float* W2   = (const float*)d_in[4];
    const float* b2   = (const float*)d_in[5];
    const float* W3   = (const float*)d_in[6];
    const float* b3   = (const float*)d_in[7];
    const float* bias = (const float*)d_in[8];
    float* out = (float*)d_out;

    cudaFuncSetAttribute(conv_kernel, cudaFuncAttributeMaxDynamicSharedMemorySize, SMEM_DYN);

    mask_kernel<<<1, 64>>>(ge);
    xt_kernel<<<dim3(64, 16, 2), 256>>>(x);
    siren_kernel<<<G_ * G_, 256>>>(ge, W1, b1, W2, b2, W3, b3);
    conv_kernel<<<512, 512, SMEM_DYN>>>(bias, out);
}

// round 6
// speedup vs baseline: 8.9695x; 1.5389x over previous
#include <cuda_runtime.h>
#include <cuda_fp16.h>
#include <math.h>
#include <stdint.h>

#define G_     8
#define KS_    7
#define NTAP_  49
#define HID_   32
#define OMEGA_ 10.0f

// ---------------------------------------------------------------------------
// Device globals (static — no allocation)
// ---------------------------------------------------------------------------
__device__ __align__(256) __half d_A[2 * NTAP_ * 4 * 128 * 64];    // 3.2MB
__device__ __align__(256) __half d_xT[16 * 4096 * 256];            // 16.8MB
__device__ int d_mask[G_ * NTAP_];
__device__ int d_utap[NTAP_];
__device__ int d_nu;

// ---------------------------------------------------------------------------
// PTX helpers (baseline sm_80-class only: compiles for .target sm_103)
// ---------------------------------------------------------------------------
__device__ __forceinline__ uint32_t smem_u32(const void* p) {
    uint32_t a;
    asm("{ .reg .u64 t; cvta.to.shared.u64 t, %1; cvt.u32.u64 %0, t; }" : "=r"(a) : "l"(p));
    return a;
}
__device__ __forceinline__ void cp16(uint32_t dst, const void* src, uint32_t sz) {
    asm volatile("cp.async.cg.shared.global [%0], [%1], 16, %2;"
                 :: "r"(dst), "l"(src), "r"(sz) : "memory");
}
#define CP_COMMIT() asm volatile("cp.async.commit_group;" ::: "memory")
#define CP_WAIT1()  asm volatile("cp.async.wait_group 1;" ::: "memory")

__device__ __forceinline__ void ldsm4(uint32_t* r, uint32_t a) {
    asm volatile("ldmatrix.sync.aligned.m8n8.x4.shared.b16 {%0,%1,%2,%3}, [%4];"
                 : "=r"(r[0]), "=r"(r[1]), "=r"(r[2]), "=r"(r[3]) : "r"(a));
}
__device__ __forceinline__ void mma16816(float* d, const uint32_t* a, const uint32_t* b) {
    asm volatile(
        "mma.sync.aligned.m16n8k16.row.col.f32.f16.f16.f32 "
        "{%0,%1,%2,%3}, {%4,%5,%6,%7}, {%8,%9}, {%0,%1,%2,%3};"
        : "+f"(d[0]), "+f"(d[1]), "+f"(d[2]), "+f"(d[3])
        : "r"(a[0]), "r"(a[1]), "r"(a[2]), "r"(a[3]), "r"(b[0]), "r"(b[1]));
}

// Replicate jnp.linspace(-1,1,7) fp32 exactly
__device__ __forceinline__ float grid_val(int i) {
    if (i == 6) return 1.0f;
    const float step = 2.0f / 6.0f;
    return __fadd_rn(__fmul_rn((float)i, step), -1.0f);
}

// ---------------------------------------------------------------------------
// Mask: per-gout disk masks + union tap list. Mirrors JAX fp32 op sequence.
// ---------------------------------------------------------------------------
__global__ void mask_kernel(const float* __restrict__ ge) {
    __shared__ int um[NTAP_];
    int t = threadIdx.x;
    if (t < NTAP_) {
        float y = grid_val(t / KS_);
        float x = grid_val(t % KS_);
        int u = 0;
        for (int g = 0; g < G_; g++) {
            float th = ge[g];
            float ct = cosf(-th), st = sinf(-th);
            float ny = __fadd_rn(__fmul_rn(ct, y), -__fmul_rn(st, x));
            float nx = __fadd_rn(__fmul_rn(st, y),  __fmul_rn(ct, x));
            float ss = __fadd_rn(__fmul_rn(ny, ny), __fmul_rn(nx, nx));
            int mk = (sqrtf(ss) <= 1.0f) ? 1 : 0;
            d_mask[g * NTAP_ + t] = mk;
            u |= mk;
        }
        um[t] = u;
    }
    __syncthreads();
    if (t == 0) {
        int n = 0;
        for (int i = 0; i < NTAP_; i++)
            if (um[i]) d_utap[n++] = i;
        d_nu = n;
    }
}

// ---------------------------------------------------------------------------
// Transpose + fp16 convert: x[b][c][pix] -> xT[b][pix][c]
// ---------------------------------------------------------------------------
__global__ void xt_kernel(const float* __restrict__ x) {
    __shared__ float s[64][129];
    int p0 = blockIdx.x * 64;
    int b  = blockIdx.y;
    int c0 = blockIdx.z * 128;
    int tid = threadIdx.x;
    int c_off = tid >> 6;
    int px = tid & 63;
    const float* xb = x + (size_t)b * 256 * 4096 + p0 + px;
#pragma unroll 4
    for (int cb = 0; cb < 32; cb++) {
        int cl = cb * 4 + c_off;
        s[px][cl] = xb[(size_t)(c0 + cl) * 4096];
    }
    __syncthreads();
#pragma unroll
    for (int r = 0; r < 4; r++) {
        int idx = tid + r * 256;       // 0..1023
        int p = idx >> 4;              // 0..63
        int u = idx & 15;              // 16 uint4 per 128-ch half
        __half hb[8];
#pragma unroll
        for (int e = 0; e < 8; e++)
            hb[e] = __float2half_rn(s[p][u * 8 + e]);
        size_t dst = ((size_t)b * 4096 + p0 + p) * 256 + c0 + u * 8;
        *(uint4*)(d_xT + dst) = *(uint4*)hb;
    }
}

// ---------------------------------------------------------------------------
// SIREN kernel-net -> masked fp16 A tiles [mt][tap][cc][m=128][k=64]
// ---------------------------------------------------------------------------
__global__ void siren_kernel(const float* __restrict__ ge,
                             const float* __restrict__ W1, const float* __restrict__ b1,
                             const float* __restrict__ W2, const float* __restrict__ b2,
                             const float* __restrict__ W3, const float* __restrict__ b3) {
    __shared__ float pts[NTAP_ * 3];
    __shared__ float h1[NTAP_ * HID_];
    __shared__ float h2[NTAP_ * HID_];
    __shared__ int   s_mask[NTAP_];

    int gout = blockIdx.x >> 3;
    int gin  = blockIdx.x & 7;
    int tid  = threadIdx.x;

    if (tid < NTAP_) {
        s_mask[tid] = d_mask[gout * NTAP_ + tid];
        float tho = ge[gout];
        float thi = ge[gin];
        float ct = cosf(-tho);
        float st = sinf(-tho);
        const float twopi = 6.28318530717958647692f;
        const float pif   = 3.14159265358979323846f;
        float d = __fadd_rn(thi, -tho);
        float m = fmodf(d, twopi);
        if (m < 0.0f) m = __fadd_rn(m, twopi);
        float ag = __fadd_rn(__fdiv_rn(m, pif), -1.0f);
        float y = grid_val(tid / KS_);
        float x = grid_val(tid % KS_);
        pts[tid * 3 + 0] = __fadd_rn(__fmul_rn(ct, y), -__fmul_rn(st, x));
        pts[tid * 3 + 1] = __fadd_rn(__fmul_rn(st, y),  __fmul_rn(ct, x));
        pts[tid * 3 + 2] = ag;
    }
    __syncthreads();

    for (int i = tid; i < NTAP_ * HID_; i += 256) {
        int t = i >> 5, h = i & 31;
        float v = b1[h];
        v = fmaf(pts[t * 3 + 0], W1[0 * HID_ + h], v);
        v = fmaf(pts[t * 3 + 1], W1[1 * HID_ + h], v);
        v = fmaf(pts[t * 3 + 2], W1[2 * HID_ + h], v);
        h1[i] = sinf(OMEGA_ * v);
    }
    __syncthreads();

    for (int i = tid; i < NTAP_ * HID_; i += 256) {
        int t = i >> 5, h = i & 31;
        float v = b2[h];
#pragma unroll
        for (int k = 0; k < HID_; k++)
            v = fmaf(h1[t * HID_ + k], W2[k * HID_ + h], v);
        h2[i] = sinf(OMEGA_ * v);
    }
    __syncthreads();

    for (int i = tid; i < NTAP_ * 1024; i += 256) {
        int t = i >> 10, o = i & 1023;
        float v = b3[o];
#pragma unroll
        for (int k = 0; k < HID_; k++)
            v = fmaf(h2[t * HID_ + k], W3[k * 1024 + o], v);
        if (!s_mask[t]) v = 0.0f;
        int cout = o >> 5, cin = o & 31;
        int c = cin * G_ + gin;
        int mt = gout >> 2, m = ((gout & 3) << 5) + cout;
        size_t addr = ((size_t)((mt * NTAP_ + t) * 4 + (c >> 6))) * 8192 + m * 64 + (c & 63);
        d_A[addr] = __float2half_rn(v);
    }
}

// ---------------------------------------------------------------------------
// HMMA conv: 512 threads / 16 warps, block tile M=128 x N=256px, warp 64x32,
// K-chunk=64 (tap x 64ch), single-term fp16, 3-stage cp.async pipeline,
// one __syncthreads per chunk.
// ---------------------------------------------------------------------------
#define ST_A     0
#define ST_B     16384
#define STAGE_SZ 49152
#define SM_BIAS  (3 * STAGE_SZ)
#define SM_UTAP  (SM_BIAS + 128)
#define SM_NU    (SM_UTAP + 4 * NTAP_)
#define SMEM_DYN (SM_NU + 16)

struct ConvCtx {
    uint32_t sbase;
    int tid, mt, b, h0;
    const int* utap;
};

__device__ __forceinline__ void stage_chunk(const ConvCtx& c, int i, int s) {
    int tap = c.utap[i >> 2];
    int cc  = i & 3;
    uint32_t stg = c.sbase + (uint32_t)s * STAGE_SZ;

    // A: [128m x 64k] rows of 128B, 16B-XOR swizzle (2 uint4/thread)
    const char* ga = (const char*)(d_A + (size_t)((c.mt * NTAP_ + tap) * 4 + cc) * 8192);
#pragma unroll
    for (int r = 0; r < 2; r++) {
        int idx = c.tid + (r << 9);
        int m = idx >> 3, u = idx & 7;
        uint32_t d = (uint32_t)(m * 128 + ((u * 16) ^ ((m & 7) << 4)));
        cp16(stg + ST_A + d, ga + idx * 16, 16);
    }
    // B: 256 pixel rows x 64k (128B); 2 threads per pixel, 4 uint4 each
    int dy = tap / KS_ - 3, dx = tap % KS_ - 3;
    int pix  = c.tid >> 1;
    int half = c.tid & 1;
    int hh = c.h0 + (pix >> 6) + dy;
    int ww = (pix & 63) + dx;
    bool ok = (hh >= 0) && (hh < 64) && (ww >= 0) && (ww < 64);
    size_t gpix = ok ? ((size_t)c.b * 4096 + (size_t)hh * 64 + ww) : 0;
    const char* gb = (const char*)(d_xT + gpix * 256 + cc * 64);
    uint32_t sz = ok ? 16u : 0u;
    uint32_t rowbase = (uint32_t)(pix * 128);
    uint32_t sw = (uint32_t)((pix & 7) << 4);
#pragma unroll
    for (int u = 0; u < 4; u++) {
        int uu = half * 4 + u;
        uint32_t d = rowbase + ((uu * 16) ^ sw);
        cp16(stg + ST_B + d, gb + uu * 16, sz);
    }
}

__global__ void __launch_bounds__(512, 1)
conv_kernel(const float* __restrict__ bias, float* __restrict__ out) {
    extern __shared__ char sm[];
    uint32_t sbase = smem_u32(sm);
    int tid  = threadIdx.x;
    int lane = tid & 31;
    int wid  = tid >> 5;
    int wm   = wid & 1;     // M half (64 rows)
    int wn   = wid >> 1;    // N 32-px block (0..7)

    if (tid < 32) ((float*)(sm + SM_BIAS))[tid] = bias[tid];
    if (tid < NTAP_) ((int*)(sm + SM_UTAP))[tid] = d_utap[tid];
    if (tid == 0) *((int*)(sm + SM_NU)) = d_nu;
    __syncthreads();

    ConvCtx c;
    c.sbase = sbase;
    c.tid = tid;
    c.utap = (const int*)(sm + SM_UTAP);
    int nu = *((const int*)(sm + SM_NU));
    int nc = nu << 2;

    int T  = blockIdx.x;
    c.mt   = T & 1;
    c.b    = (T >> 1) & 15;
    c.h0   = (T >> 5) << 2;

    float acc[4][4][4];
#pragma unroll
    for (int ms = 0; ms < 4; ms++)
#pragma unroll
        for (int nf = 0; nf < 4; nf++)
#pragma unroll
            for (int q = 0; q < 4; q++) acc[ms][nf][q] = 0.0f;

    stage_chunk(c, 0, 0);
    CP_COMMIT();
    stage_chunk(c, 1, 1);
    CP_COMMIT();

    int s = 0;
    for (int i = 0; i < nc; i++) {
        CP_WAIT1();                 // stage i resident (i+1 may be in flight)
        __syncthreads();            // also: everyone finished compute(i-1)
        if (i + 2 < nc) {           // prefetch into buffer (i+2)%3 == (i-1)%3
            int s2 = s + 2; if (s2 >= 3) s2 -= 3;
            stage_chunk(c, i + 2, s2);
            CP_COMMIT();
        }

        uint32_t stg = sbase + (uint32_t)s * STAGE_SZ;
#pragma unroll
        for (int ks = 0; ks < 4; ks++) {
            uint32_t af[4][4], bf[2][4];
#pragma unroll
            for (int ms = 0; ms < 4; ms++) {
                int row = wm * 64 + ms * 16 + (lane & 15);
                uint32_t kb = (uint32_t)(ks * 32 + ((lane >> 4) << 4));
                uint32_t a = stg + (uint32_t)(row * 128) + (kb ^ ((row & 7) << 4));
                ldsm4(af[ms], a + ST_A);
            }
#pragma unroll
            for (int ns = 0; ns < 2; ns++) {
                int row = wn * 32 + ns * 16 + (lane & 7) + ((lane & 16) >> 1);
                uint32_t kb = (uint32_t)(ks * 32 + ((lane & 8) << 1));
                uint32_t a = stg + (uint32_t)(row * 128) + (kb ^ ((row & 7) << 4));
                ldsm4(bf[ns], a + ST_B);
            }
#pragma unroll
            for (int ms = 0; ms < 4; ms++)
#pragma unroll
                for (int nf = 0; nf < 4; nf++)
                    mma16816(acc[ms][nf], af[ms], &bf[nf >> 1][(nf & 1) * 2]);
        }
        if (++s >= 3) s = 0;
    }

    // epilogue: out[b][cout][gout][h][w] + bias[cout]
    const float* sb = (const float*)(sm + SM_BIAS);
    int h = c.h0 + (wn >> 1);
    int wbase = (wn & 1) * 32;
#pragma unroll
    for (int ms = 0; ms < 4; ms++) {
#pragma unroll
        for (int half = 0; half < 2; half++) {
            int rm = wm * 64 + ms * 16 + (lane >> 2) + half * 8;
            int gout = c.mt * 4 + (rm >> 5);
            int cout = rm & 31;
            float bv = sb[cout];
            float* ob = out + (((size_t)c.b * 32 + cout) * 8 + gout) * 4096 + h * 64;
#pragma unroll
            for (int nf = 0; nf < 4; nf++) {
                int w = wbase + nf * 8 + (lane & 3) * 2;
                float2 v;
                v.x = acc[ms][nf][half * 2 + 0] + bv;
                v.y = acc[ms][nf][half * 2 + 1] + bv;
                *(float2*)(ob + w) = v;
            }
        }
    }
}

// ---------------------------------------------------------------------------
extern "C" void kernel_launch(void* const* d_in, const int* in_sizes, int n_in,
                              void* d_out, int out_size) {
    const float* x    = (const float*)d_in[0];
    const float* ge   = (const float*)d_in[1];
    const float* W1   = (const float*)d_in[2];
    const float* b1   = (const float*)d_in[3];
    const float* W2   = (const float*)d_in[4];
    const float* b2   = (const float*)d_in[5];
    const float* W3   = (const float*)d_in[6];
    const float* b3   = (const float*)d_in[7];
    const float* bias = (const float*)d_in[8];
    float* out = (float*)d_out;

    cudaFuncSetAttribute(conv_kernel, cudaFuncAttributeMaxDynamicSharedMemorySize, SMEM_DYN);

    mask_kernel<<<1, 64>>>(ge);
    xt_kernel<<<dim3(64, 16, 2), 256>>>(x);
    siren_kernel<<<G_ * G_, 256>>>(ge, W1, b1, W2, b2, W3, b3);
    conv_kernel<<<512, 512, SMEM_DYN>>>(bias, out);
}